// round 4
// baseline (speedup 1.0000x reference)
#include <cuda_runtime.h>
#include <math.h>
#include <stdint.h>
#include <stddef.h>

// ---------------------------------------------------------------------------
// LagunaMoE: router + top-4 grouped MoE (routed experts) + shared expert
// T=2048, H=2048, E=16, K=4, I=1408, IS=5632, scale=2.5, softcap=30
// ---------------------------------------------------------------------------

#define T_TOK 2048
#define HID   2048
#define NEXP  16
#define TOPK  4
#define IDIM  1408
#define ISH   5632

// -------------------- device scratch (static, allocation-free) -------------
__device__ float g_sgu  [(size_t)T_TOK * (2 * ISH)];   // shared gate_up out   [2048, 11264]
__device__ float g_sact [(size_t)T_TOK * ISH];         // shared act           [2048, 5632]
__device__ float g_sdown[(size_t)T_TOK * HID];         // shared expert out    [2048, 2048]
__device__ float g_rgu  [(size_t)T_TOK * TOPK * (2 * IDIM)]; // routed gate_up [8192, 2816]
__device__ float g_ract [(size_t)T_TOK * TOPK * IDIM]; // routed act           [8192, 1408]
__device__ float g_rdown[(size_t)T_TOK * TOPK * HID];  // routed down out      [8192, 2048]

__device__ int   g_topk_ids[T_TOK * TOPK];
__device__ float g_topk_w  [T_TOK * TOPK];
__device__ int   g_counts[NEXP];
__device__ int   g_offs  [NEXP + 1];
__device__ int   g_cursor[NEXP];
__device__ int   g_perm  [T_TOK * TOPK];   // perm row -> token
__device__ int   g_rowof [T_TOK * TOPK];   // (token, k) -> perm row

// -------------------- small kernels ----------------------------------------
__global__ void zero_counts_kernel() {
    if (threadIdx.x < NEXP) g_counts[threadIdx.x] = 0;
}

__global__ __launch_bounds__(256) void router_kernel(
    const float* __restrict__ x, const float* __restrict__ gw,
    const float* __restrict__ bias)
{
    const int t = blockIdx.x;
    const float* xr = x + (size_t)t * HID;

    float acc[NEXP];
#pragma unroll
    for (int e = 0; e < NEXP; e++) acc[e] = 0.f;

    for (int h = threadIdx.x; h < HID; h += 256) {
        const float xv = xr[h];
#pragma unroll
        for (int e = 0; e < NEXP; e++)
            acc[e] = fmaf(xv, gw[e * HID + h], acc[e]);
    }
#pragma unroll
    for (int e = 0; e < NEXP; e++) {
        float v = acc[e];
#pragma unroll
        for (int off = 16; off > 0; off >>= 1)
            v += __shfl_xor_sync(0xffffffffu, v, off);
        acc[e] = v;
    }

    __shared__ float red[NEXP][8];
    __shared__ float s_score[NEXP], s_sel[NEXP];
    const int warp = threadIdx.x >> 5, lane = threadIdx.x & 31;
    if (lane == 0) {
#pragma unroll
        for (int e = 0; e < NEXP; e++) red[e][warp] = acc[e];
    }
    __syncthreads();
    if (threadIdx.x < NEXP) {
        float v = 0.f;
#pragma unroll
        for (int w = 0; w < 8; w++) v += red[threadIdx.x][w];
        v = tanhf(v * (1.0f / 30.0f)) * 30.0f;           // softcap
        const float sc = 1.0f / (1.0f + expf(-v));       // sigmoid score
        s_score[threadIdx.x] = sc;
        s_sel[threadIdx.x]   = sc + bias[threadIdx.x];   // selection uses bias
    }
    __syncthreads();
    if (threadIdx.x == 0) {
        int ids[TOPK]; float ws[TOPK]; float wsum = 0.f;
        unsigned used = 0;
        for (int k = 0; k < TOPK; k++) {
            int best = 0; float bv = -1e30f;
            for (int e = 0; e < NEXP; e++) {
                if (!((used >> e) & 1u) && s_sel[e] > bv) { bv = s_sel[e]; best = e; }
            }
            used |= (1u << best);
            ids[k] = best; ws[k] = s_score[best]; wsum += s_score[best];
        }
        const float inv = 1.0f / wsum;
        for (int k = 0; k < TOPK; k++) {
            g_topk_ids[t * TOPK + k] = ids[k];
            g_topk_w  [t * TOPK + k] = ws[k] * inv;
            atomicAdd(&g_counts[ids[k]], 1);
        }
    }
}

__global__ void scan_kernel() {
    if (threadIdx.x == 0) {
        int s = 0;
        for (int e = 0; e < NEXP; e++) {
            g_offs[e] = s; s += g_counts[e]; g_cursor[e] = 0;
        }
        g_offs[NEXP] = s;
    }
}

__global__ void build_perm_kernel() {
    const int t = blockIdx.x * blockDim.x + threadIdx.x;
    if (t >= T_TOK) return;
    for (int k = 0; k < TOPK; k++) {
        const int e = g_topk_ids[t * TOPK + k];
        const int pos = g_offs[e] + atomicAdd(&g_cursor[e], 1);
        g_perm[pos] = t;
        g_rowof[t * TOPK + k] = pos;
    }
}

// -------------------- 128x128x8 double-buffered SGEMM ----------------------
// MODE 0: plain C = A @ B                (M given, dense)
// MODE 1: grouped (blockIdx.z = expert): rows [offs[e], offs[e+1]) of A/C,
//         B advanced by e*bstride       (A rows are perm-space: no indirect)
// MODE 2: grouped + A-row indirection through g_perm (A = token matrix)
template <int MODE>
__global__ __launch_bounds__(256) void sgemm128_kernel(
    const float* __restrict__ A, int lda,
    const float* __restrict__ B, int ldb, size_t bstride,
    float* __restrict__ C, int ldc,
    int M, int K)
{
    int rowOff = 0;
    int Mloc = M;
    const float* Bp = B;
    if (MODE >= 1) {
        const int e = blockIdx.z;
        rowOff = g_offs[e];
        Mloc = g_offs[e + 1] - rowOff;
        Bp += (size_t)e * bstride;
    }
    const int m0 = blockIdx.y * 128;
    if (m0 >= Mloc) return;
    const int n0 = blockIdx.x * 128;

    __shared__ float As[2][8][128];
    __shared__ float Bs[2][8][128];

    const int tid = threadIdx.x;
    const int tx = tid & 15;
    const int ty = tid >> 4;

    const int aRow = tid >> 1;           // 0..127
    const int aK   = (tid & 1) << 2;     // 0 or 4
    const int bK   = tid >> 5;           // 0..7
    const int bN   = (tid & 31) << 2;    // 0..124

    const int rA  = m0 + aRow;
    const int rCl = (rA < Mloc) ? rA : (Mloc - 1);
    const float* Aptr;
    if (MODE == 2)      Aptr = A + (size_t)g_perm[rowOff + rCl] * lda + aK;
    else if (MODE == 1) Aptr = A + (size_t)(rowOff + rCl) * lda + aK;
    else                Aptr = A + (size_t)rCl * lda + aK;

    const float* Bptr = Bp + (size_t)bK * ldb + n0 + bN;

    float acc[8][8];
#pragma unroll
    for (int i = 0; i < 8; i++)
#pragma unroll
        for (int j = 0; j < 8; j++) acc[i][j] = 0.f;

    const int nkt = K >> 3;

    {
        float4 a = *(const float4*)Aptr;
        float4 b = *(const float4*)Bptr;
        As[0][aK + 0][aRow] = a.x; As[0][aK + 1][aRow] = a.y;
        As[0][aK + 2][aRow] = a.z; As[0][aK + 3][aRow] = a.w;
        *(float4*)&Bs[0][bK][bN] = b;
    }
    __syncthreads();

    for (int kt = 0; kt < nkt; ++kt) {
        const int buf = kt & 1;
        float4 an, bn;
        const bool more = (kt + 1 < nkt);
        if (more) {
            an = *(const float4*)(Aptr + (size_t)(kt + 1) * 8);
            bn = *(const float4*)(Bptr + (size_t)(kt + 1) * 8 * ldb);
        }
#pragma unroll
        for (int k = 0; k < 8; k++) {
            float ar[8], br[8];
            *(float4*)&ar[0] = *(const float4*)&As[buf][k][ty * 8];
            *(float4*)&ar[4] = *(const float4*)&As[buf][k][ty * 8 + 4];
            *(float4*)&br[0] = *(const float4*)&Bs[buf][k][tx * 8];
            *(float4*)&br[4] = *(const float4*)&Bs[buf][k][tx * 8 + 4];
#pragma unroll
            for (int i = 0; i < 8; i++)
#pragma unroll
                for (int j = 0; j < 8; j++)
                    acc[i][j] = fmaf(ar[i], br[j], acc[i][j]);
        }
        if (more) {
            const int nb = buf ^ 1;
            As[nb][aK + 0][aRow] = an.x; As[nb][aK + 1][aRow] = an.y;
            As[nb][aK + 2][aRow] = an.z; As[nb][aK + 3][aRow] = an.w;
            *(float4*)&Bs[nb][bK][bN] = bn;
            __syncthreads();
        }
    }

#pragma unroll
    for (int i = 0; i < 8; i++) {
        const int r = m0 + ty * 8 + i;
        if (MODE >= 1 && r >= Mloc) continue;
        float* cp = C + (size_t)(rowOff + r) * ldc + n0 + tx * 8;
        *(float4*)(cp)     = make_float4(acc[i][0], acc[i][1], acc[i][2], acc[i][3]);
        *(float4*)(cp + 4) = make_float4(acc[i][4], acc[i][5], acc[i][6], acc[i][7]);
    }
}

// -------------------- elementwise -----------------------------------------
__global__ void swiglu_kernel(const float* __restrict__ gu, float* __restrict__ act,
                              int icols, int nTotal)
{
    const int idx = blockIdx.x * 256 + threadIdx.x;
    if (idx >= nTotal) return;
    const int r = idx / icols;
    const int c = idx - r * icols;
    const size_t base = (size_t)r * (2 * icols);
    const float g = gu[base + c];
    const float u = gu[base + icols + c];
    act[idx] = (g / (1.0f + expf(-g))) * u;   // silu(g) * u
}

__global__ void combine_kernel(float* __restrict__ out, const float* __restrict__ sdown)
{
    const int idx = blockIdx.x * 256 + threadIdx.x;   // exactly T*H elems
    const int t = idx >> 11;
    const int h = idx & (HID - 1);
    float r = 0.f;
#pragma unroll
    for (int k = 0; k < TOPK; k++) {
        const int pos = g_rowof[t * TOPK + k];
        r = fmaf(g_topk_w[t * TOPK + k], g_rdown[(size_t)pos * HID + h], r);
    }
    out[idx] = fmaf(2.5f, r, sdown[idx]);
}

// -------------------- launch -----------------------------------------------
extern "C" void kernel_launch(void* const* d_in, const int* in_sizes, int n_in,
                              void* d_out, int out_size)
{
    const float* x    = (const float*)d_in[0];   // [T, H]
    const float* gw   = (const float*)d_in[1];   // [E, H]
    const float* cb   = (const float*)d_in[2];   // [E]
    const float* wgu  = (const float*)d_in[3];   // [E, H, 2I]
    const float* wdn  = (const float*)d_in[4];   // [E, I, H]
    const float* swgu = (const float*)d_in[5];   // [H, 2*IS]
    const float* swdn = (const float*)d_in[6];   // [IS, H]
    float* out = (float*)d_out;
    (void)in_sizes; (void)n_in; (void)out_size;

    float *p_sgu, *p_sact, *p_sdown, *p_rgu, *p_ract, *p_rdown;
    cudaGetSymbolAddress((void**)&p_sgu,   g_sgu);
    cudaGetSymbolAddress((void**)&p_sact,  g_sact);
    cudaGetSymbolAddress((void**)&p_sdown, g_sdown);
    cudaGetSymbolAddress((void**)&p_rgu,   g_rgu);
    cudaGetSymbolAddress((void**)&p_ract,  g_ract);
    cudaGetSymbolAddress((void**)&p_rdown, g_rdown);

    // ---- routing ----
    zero_counts_kernel<<<1, 32>>>();
    router_kernel<<<T_TOK, 256>>>(x, gw, cb);
    scan_kernel<<<1, 32>>>();
    build_perm_kernel<<<(T_TOK + 255) / 256, 256>>>();

    // ---- routed experts (grouped) ----
    // gate_up: xg[perm] @ w_gate_up[e]  ->  g_rgu [8192, 2816]
    sgemm128_kernel<2><<<dim3(2 * IDIM / 128, 16, NEXP), 256>>>(
        x, HID, wgu, 2 * IDIM, (size_t)HID * 2 * IDIM, p_rgu, 2 * IDIM, 0, HID);
    swiglu_kernel<<<(T_TOK * TOPK * IDIM + 255) / 256, 256>>>(
        p_rgu, p_ract, IDIM, T_TOK * TOPK * IDIM);
    // down: act @ w_down[e] -> g_rdown [8192, 2048]
    sgemm128_kernel<1><<<dim3(HID / 128, 16, NEXP), 256>>>(
        p_ract, IDIM, wdn, HID, (size_t)IDIM * HID, p_rdown, HID, 0, IDIM);

    // ---- shared expert ----
    sgemm128_kernel<0><<<dim3(2 * ISH / 128, T_TOK / 128, 1), 256>>>(
        x, HID, swgu, 2 * ISH, 0, p_sgu, 2 * ISH, T_TOK, HID);
    swiglu_kernel<<<(T_TOK * ISH + 255) / 256, 256>>>(
        p_sgu, p_sact, ISH, T_TOK * ISH);
    sgemm128_kernel<0><<<dim3(HID / 128, T_TOK / 128, 1), 256>>>(
        p_sact, ISH, swdn, HID, 0, p_sdown, HID, T_TOK, ISH);

    // ---- combine: out = 2.5 * routed + shared ----
    combine_kernel<<<(T_TOK * HID) / 256, 256>>>(out, p_sdown);
}

// round 5
// speedup vs baseline: 2.5158x; 2.5158x over previous
#include <cuda_runtime.h>
#include <math.h>
#include <stdint.h>
#include <stddef.h>

// ---------------------------------------------------------------------------
// LagunaMoE: router + top-4 grouped MoE (routed experts) + shared expert
// T=2048, H=2048, E=16, K=4, I=1408, IS=5632, scale=2.5, softcap=30
// R4: tf32 tensor-core GEMM (mma.sync m16n8k8) replaces FFMA SGEMM.
// ---------------------------------------------------------------------------

#define T_TOK 2048
#define HID   2048
#define NEXP  16
#define TOPK  4
#define IDIM  1408
#define ISH   5632

// -------------------- device scratch (static, allocation-free) -------------
__device__ float g_sgu  [(size_t)T_TOK * (2 * ISH)];
__device__ float g_sact [(size_t)T_TOK * ISH];
__device__ float g_sdown[(size_t)T_TOK * HID];
__device__ float g_rgu  [(size_t)T_TOK * TOPK * (2 * IDIM)];
__device__ float g_ract [(size_t)T_TOK * TOPK * IDIM];
__device__ float g_rdown[(size_t)T_TOK * TOPK * HID];

__device__ int   g_topk_ids[T_TOK * TOPK];
__device__ float g_topk_w  [T_TOK * TOPK];
__device__ int   g_counts[NEXP];
__device__ int   g_offs  [NEXP + 1];
__device__ int   g_cursor[NEXP];
__device__ int   g_perm  [T_TOK * TOPK];
__device__ int   g_rowof [T_TOK * TOPK];

// -------------------- small kernels ----------------------------------------
__global__ void zero_counts_kernel() {
    if (threadIdx.x < NEXP) g_counts[threadIdx.x] = 0;
}

__global__ __launch_bounds__(256) void router_kernel(
    const float* __restrict__ x, const float* __restrict__ gw,
    const float* __restrict__ bias)
{
    const int t = blockIdx.x;
    const float* xr = x + (size_t)t * HID;

    float acc[NEXP];
#pragma unroll
    for (int e = 0; e < NEXP; e++) acc[e] = 0.f;

    for (int h = threadIdx.x; h < HID; h += 256) {
        const float xv = xr[h];
#pragma unroll
        for (int e = 0; e < NEXP; e++)
            acc[e] = fmaf(xv, gw[e * HID + h], acc[e]);
    }
#pragma unroll
    for (int e = 0; e < NEXP; e++) {
        float v = acc[e];
#pragma unroll
        for (int off = 16; off > 0; off >>= 1)
            v += __shfl_xor_sync(0xffffffffu, v, off);
        acc[e] = v;
    }

    __shared__ float red[NEXP][8];
    __shared__ float s_score[NEXP], s_sel[NEXP];
    const int warp = threadIdx.x >> 5, lane = threadIdx.x & 31;
    if (lane == 0) {
#pragma unroll
        for (int e = 0; e < NEXP; e++) red[e][warp] = acc[e];
    }
    __syncthreads();
    if (threadIdx.x < NEXP) {
        float v = 0.f;
#pragma unroll
        for (int w = 0; w < 8; w++) v += red[threadIdx.x][w];
        v = tanhf(v * (1.0f / 30.0f)) * 30.0f;
        const float sc = 1.0f / (1.0f + expf(-v));
        s_score[threadIdx.x] = sc;
        s_sel[threadIdx.x]   = sc + bias[threadIdx.x];
    }
    __syncthreads();
    if (threadIdx.x == 0) {
        int ids[TOPK]; float ws[TOPK]; float wsum = 0.f;
        unsigned used = 0;
        for (int k = 0; k < TOPK; k++) {
            int best = 0; float bv = -1e30f;
            for (int e = 0; e < NEXP; e++) {
                if (!((used >> e) & 1u) && s_sel[e] > bv) { bv = s_sel[e]; best = e; }
            }
            used |= (1u << best);
            ids[k] = best; ws[k] = s_score[best]; wsum += s_score[best];
        }
        const float inv = 1.0f / wsum;
        for (int k = 0; k < TOPK; k++) {
            g_topk_ids[t * TOPK + k] = ids[k];
            g_topk_w  [t * TOPK + k] = ws[k] * inv;
            atomicAdd(&g_counts[ids[k]], 1);
        }
    }
}

__global__ void scan_kernel() {
    if (threadIdx.x == 0) {
        int s = 0;
        for (int e = 0; e < NEXP; e++) {
            g_offs[e] = s; s += g_counts[e]; g_cursor[e] = 0;
        }
        g_offs[NEXP] = s;
    }
}

__global__ void build_perm_kernel() {
    const int t = blockIdx.x * blockDim.x + threadIdx.x;
    if (t >= T_TOK) return;
    for (int k = 0; k < TOPK; k++) {
        const int e = g_topk_ids[t * TOPK + k];
        const int pos = g_offs[e] + atomicAdd(&g_cursor[e], 1);
        g_perm[pos] = t;
        g_rowof[t * TOPK + k] = pos;
    }
}

// -------------------- tf32 tensor-core helpers -----------------------------
__device__ __forceinline__ uint32_t f2tf(float f) {
    uint32_t u;
    asm("cvt.rna.tf32.f32 %0, %1;" : "=r"(u) : "f"(f));
    return u;
}

__device__ __forceinline__ void mma_tf32(float* c, const uint32_t* a,
                                         uint32_t b0, uint32_t b1) {
    asm volatile(
        "mma.sync.aligned.m16n8k8.row.col.f32.tf32.tf32.f32 "
        "{%0,%1,%2,%3}, {%4,%5,%6,%7}, {%8,%9}, {%0,%1,%2,%3};"
        : "+f"(c[0]), "+f"(c[1]), "+f"(c[2]), "+f"(c[3])
        : "r"(a[0]), "r"(a[1]), "r"(a[2]), "r"(a[3]), "r"(b0), "r"(b1));
}

__device__ __forceinline__ void cp16(uint32_t dst, const void* src) {
    asm volatile("cp.async.cg.shared.global [%0], [%1], 16;\n" :: "r"(dst), "l"(src));
}
__device__ __forceinline__ void cp_commit() {
    asm volatile("cp.async.commit_group;\n");
}
__device__ __forceinline__ void cp_wait0() {
    asm volatile("cp.async.wait_group 0;\n");
}

// -------------------- 128x128x16 tf32 tensor-core GEMM ---------------------
// MODE 0: plain C = A @ B
// MODE 1: grouped (blockIdx.z = expert): rows [offs[e], offs[e+1]) of A/C
// MODE 2: grouped + A-row indirection through g_perm
#define AS_STRIDE 20
#define BS_STRIDE 136
template <int MODE>
__global__ __launch_bounds__(256, 2) void gemm_tc_kernel(
    const float* __restrict__ A, int lda,
    const float* __restrict__ B, int ldb, size_t bstride,
    float* __restrict__ C, int ldc,
    int M, int K)
{
    int rowOff = 0;
    int Mloc = M;
    const float* Bp = B;
    if (MODE >= 1) {
        const int e = blockIdx.z;
        rowOff = g_offs[e];
        Mloc = g_offs[e + 1] - rowOff;
        Bp += (size_t)e * bstride;
    }
    const int m0 = blockIdx.y * 128;
    if (m0 >= Mloc) return;
    const int n0 = blockIdx.x * 128;

    __shared__ float As[2][128][AS_STRIDE];   // [m][k], k-contiguous, pad 4
    __shared__ float Bs[2][16][BS_STRIDE];    // [k][n], n-contiguous, pad 8

    const int tid = threadIdx.x;
    const int l   = tid & 31;
    const int w   = tid >> 5;
    const int mw  = (w & 3) * 32;    // warp m offset in tile
    const int nw  = (w >> 2) * 64;   // warp n offset in tile

    // ---- staging assignments ----
    // A: thread -> row = tid>>1 (0..127), kcol = (tid&1)*8; two 16B chunks
    const int aRow = tid >> 1;
    const int aKc  = (tid & 1) * 8;
    const int aRowC = (m0 + aRow < Mloc) ? (m0 + aRow) : (Mloc - 1);
    const float* gA;
    if (MODE == 2)      gA = A + (size_t)g_perm[rowOff + aRowC] * lda + aKc;
    else if (MODE == 1) gA = A + (size_t)(rowOff + aRowC) * lda + aKc;
    else                gA = A + (size_t)aRowC * lda + aKc;
    // B: thread -> krow = tid>>4 (0..15), ncol = (tid&15)*8; two 16B chunks
    const int bK = tid >> 4;
    const int bN = (tid & 15) * 8;
    const float* gB = Bp + (size_t)bK * ldb + n0 + bN;

    uint32_t sA0[2], sA1[2], sB0[2], sB1[2];
#pragma unroll
    for (int s = 0; s < 2; s++) {
        sA0[s] = (uint32_t)__cvta_generic_to_shared(&As[s][aRow][aKc]);
        sA1[s] = (uint32_t)__cvta_generic_to_shared(&As[s][aRow][aKc + 4]);
        sB0[s] = (uint32_t)__cvta_generic_to_shared(&Bs[s][bK][bN]);
        sB1[s] = (uint32_t)__cvta_generic_to_shared(&Bs[s][bK][bN + 4]);
    }

    float acc[2][8][4];
#pragma unroll
    for (int i = 0; i < 2; i++)
#pragma unroll
        for (int j = 0; j < 8; j++)
#pragma unroll
            for (int q = 0; q < 4; q++) acc[i][j][q] = 0.f;

    const int nkt = K >> 4;   // 16-wide K stages

    // prologue: stage 0
    cp16(sA0[0], gA);
    cp16(sA1[0], gA + 4);
    cp16(sB0[0], gB);
    cp16(sB1[0], gB + 4);
    cp_commit();

    // precompute ldmatrix A base row/col per thread
    const int lmRow = (l & 7) + ((l & 8) ? 8 : 0);
    const int lmCol = (l & 16) ? 4 : 0;

    for (int kt = 0; kt < nkt; ++kt) {
        cp_wait0();
        __syncthreads();
        const int buf = kt & 1;

        if (kt + 1 < nkt) {
            const float* nA = gA + (size_t)(kt + 1) * 16;
            const float* nB = gB + (size_t)(kt + 1) * 16 * ldb;
            const int nb = buf ^ 1;
            cp16(sA0[nb], nA);
            cp16(sA1[nb], nA + 4);
            cp16(sB0[nb], nB);
            cp16(sB1[nb], nB + 4);
            cp_commit();
        }

#pragma unroll
        for (int ks = 0; ks < 2; ks++) {
            uint32_t a[2][4];
#pragma unroll
            for (int i = 0; i < 2; i++) {
                uint32_t addr = (uint32_t)__cvta_generic_to_shared(
                    &As[buf][mw + 16 * i + lmRow][ks * 8 + lmCol]);
                asm volatile(
                    "ldmatrix.sync.aligned.m8n8.x4.shared.b16 {%0,%1,%2,%3}, [%4];"
                    : "=r"(a[i][0]), "=r"(a[i][1]), "=r"(a[i][2]), "=r"(a[i][3])
                    : "r"(addr));
#pragma unroll
                for (int q = 0; q < 4; q++)
                    a[i][q] = f2tf(__uint_as_float(a[i][q]));
            }
            uint32_t bf[8][2];
#pragma unroll
            for (int j = 0; j < 8; j++) {
                const int n = nw + 8 * j + (l >> 2);
                bf[j][0] = f2tf(Bs[buf][ks * 8 + (l & 3)][n]);
                bf[j][1] = f2tf(Bs[buf][ks * 8 + 4 + (l & 3)][n]);
            }
#pragma unroll
            for (int i = 0; i < 2; i++)
#pragma unroll
                for (int j = 0; j < 8; j++)
                    mma_tf32(acc[i][j], a[i], bf[j][0], bf[j][1]);
        }
        __syncthreads();
    }

    // ---- epilogue ----
#pragma unroll
    for (int i = 0; i < 2; i++) {
        const int r0 = m0 + mw + 16 * i + (l >> 2);
        const int r1 = r0 + 8;
        const int colb = n0 + nw + 2 * (l & 3);
        if (r0 < Mloc) {
            float* cp = C + (size_t)(rowOff + r0) * ldc + colb;
#pragma unroll
            for (int j = 0; j < 8; j++)
                *(float2*)(cp + 8 * j) = make_float2(acc[i][j][0], acc[i][j][1]);
        }
        if (r1 < Mloc) {
            float* cp = C + (size_t)(rowOff + r1) * ldc + colb;
#pragma unroll
            for (int j = 0; j < 8; j++)
                *(float2*)(cp + 8 * j) = make_float2(acc[i][j][2], acc[i][j][3]);
        }
    }
}

// -------------------- elementwise -----------------------------------------
__global__ void swiglu_kernel(const float* __restrict__ gu, float* __restrict__ act,
                              int icols, int nTotal)
{
    const int idx = blockIdx.x * 256 + threadIdx.x;
    if (idx >= nTotal) return;
    const int r = idx / icols;
    const int c = idx - r * icols;
    const size_t base = (size_t)r * (2 * icols);
    const float g = gu[base + c];
    const float u = gu[base + icols + c];
    act[idx] = (g / (1.0f + expf(-g))) * u;
}

__global__ void combine_kernel(float* __restrict__ out, const float* __restrict__ sdown)
{
    const int idx = blockIdx.x * 256 + threadIdx.x;
    const int t = idx >> 11;
    const int h = idx & (HID - 1);
    float r = 0.f;
#pragma unroll
    for (int k = 0; k < TOPK; k++) {
        const int pos = g_rowof[t * TOPK + k];
        r = fmaf(g_topk_w[t * TOPK + k], g_rdown[(size_t)pos * HID + h], r);
    }
    out[idx] = fmaf(2.5f, r, sdown[idx]);
}

// -------------------- launch -----------------------------------------------
extern "C" void kernel_launch(void* const* d_in, const int* in_sizes, int n_in,
                              void* d_out, int out_size)
{
    const float* x    = (const float*)d_in[0];   // [T, H]
    const float* gw   = (const float*)d_in[1];   // [E, H]
    const float* cb   = (const float*)d_in[2];   // [E]
    const float* wgu  = (const float*)d_in[3];   // [E, H, 2I]
    const float* wdn  = (const float*)d_in[4];   // [E, I, H]
    const float* swgu = (const float*)d_in[5];   // [H, 2*IS]
    const float* swdn = (const float*)d_in[6];   // [IS, H]
    float* out = (float*)d_out;
    (void)in_sizes; (void)n_in; (void)out_size;

    float *p_sgu, *p_sact, *p_sdown, *p_rgu, *p_ract, *p_rdown;
    cudaGetSymbolAddress((void**)&p_sgu,   g_sgu);
    cudaGetSymbolAddress((void**)&p_sact,  g_sact);
    cudaGetSymbolAddress((void**)&p_sdown, g_sdown);
    cudaGetSymbolAddress((void**)&p_rgu,   g_rgu);
    cudaGetSymbolAddress((void**)&p_ract,  g_ract);
    cudaGetSymbolAddress((void**)&p_rdown, g_rdown);

    // ---- routing ----
    zero_counts_kernel<<<1, 32>>>();
    router_kernel<<<T_TOK, 256>>>(x, gw, cb);
    scan_kernel<<<1, 32>>>();
    build_perm_kernel<<<(T_TOK + 255) / 256, 256>>>();

    // ---- routed experts (grouped, tf32 TC) ----
    gemm_tc_kernel<2><<<dim3(2 * IDIM / 128, 16, NEXP), 256>>>(
        x, HID, wgu, 2 * IDIM, (size_t)HID * 2 * IDIM, p_rgu, 2 * IDIM, 0, HID);
    swiglu_kernel<<<(T_TOK * TOPK * IDIM + 255) / 256, 256>>>(
        p_rgu, p_ract, IDIM, T_TOK * TOPK * IDIM);
    gemm_tc_kernel<1><<<dim3(HID / 128, 16, NEXP), 256>>>(
        p_ract, IDIM, wdn, HID, (size_t)IDIM * HID, p_rdown, HID, 0, IDIM);

    // ---- shared expert (tf32 TC) ----
    gemm_tc_kernel<0><<<dim3(2 * ISH / 128, T_TOK / 128, 1), 256>>>(
        x, HID, swgu, 2 * ISH, 0, p_sgu, 2 * ISH, T_TOK, HID);
    swiglu_kernel<<<(T_TOK * ISH + 255) / 256, 256>>>(
        p_sgu, p_sact, ISH, T_TOK * ISH);
    gemm_tc_kernel<0><<<dim3(HID / 128, T_TOK / 128, 1), 256>>>(
        p_sact, ISH, swdn, HID, 0, p_sdown, HID, T_TOK, ISH);

    // ---- combine: out = 2.5 * routed + shared ----
    combine_kernel<<<(T_TOK * HID) / 256, 256>>>(out, p_sdown);
}